// round 15
// baseline (speedup 1.0000x reference)
#include <cuda_runtime.h>
#include <cuda_fp16.h>
#include <cstdint>
#include <cstddef>
#include <math.h>

#define H_DIM 256
#define MAXV 10000
#define MAXE 160000
#define LN_EPS 1e-5f

__device__ float  g_nodebuf[(size_t)MAXV * 1024];  // [ -- | Vh | Ah | Bh]
__device__ float  g_agg[(size_t)MAXV * H_DIM];     // Uh+bias, then += gated agg
__device__ __half g_enew[(size_t)MAXE * H_DIM];    // fp16 e_new
__device__ float2 g_lns[2 * MAXE];                 // per-half LN partial (sum, sq)
__device__ float  g_wtf[5 * 65536];                // tf32 [Wu|Wv|Wa|Wb|Wc]
__device__ int    g_tile_ctr[16];

__device__ __forceinline__ void red_add_v2(float* addr, float a, float b) {
    asm volatile("red.global.add.v2.f32 [%0], {%1,%2};"
                 :: "l"(addr), "f"(a), "f"(b));
}

__device__ __forceinline__ float to_tf32(float x) {
    float y;
    asm("cvt.rna.tf32.f32 %0, %1;" : "=f"(y) : "f"(x));
    return y;
}

__device__ __forceinline__ float4 tf32_4(float4 v) {
    return make_float4(to_tf32(v.x), to_tf32(v.y), to_tf32(v.z), to_tf32(v.w));
}

__device__ __forceinline__ void mma_tf32(float& d0, float& d1, float& d2, float& d3,
                                         float a0, float a1, float a2, float a3,
                                         float b0, float b1) {
    asm volatile(
        "mma.sync.aligned.m16n8k8.row.col.f32.tf32.tf32.f32 "
        "{%0,%1,%2,%3}, {%4,%5,%6,%7}, {%8,%9}, {%0,%1,%2,%3};\n"
        : "+f"(d0), "+f"(d1), "+f"(d2), "+f"(d3)
        : "r"(__float_as_uint(a0)), "r"(__float_as_uint(a1)),
          "r"(__float_as_uint(a2)), "r"(__float_as_uint(a3)),
          "r"(__float_as_uint(b0)), "r"(__float_as_uint(b1)));
}

__device__ __forceinline__ void cpa16(uint32_t saddr, const void* g) {
    asm volatile("cp.async.cg.shared.global [%0], [%1], 16;" :: "r"(saddr), "l"(g));
}
__device__ __forceinline__ void cpa_commit() {
    asm volatile("cp.async.commit_group;");
}
template <int N>
__device__ __forceinline__ void cpa_wait() {
    asm volatile("cp.async.wait_group %0;" :: "n"(N));
}

#define SA_STRIDE 36
#define EB_STRIDE 260

#define PG_B_OFF 0
#define PG_A_OFF 33280
#define PG_A_BUF 9216
#define PG_SMEM_BYTES 206848

// ---------------------------------------------------------------------------
// Kernel 0: init — tf32 weights + reset counters.
// ---------------------------------------------------------------------------
__global__ void init_kernel(
    const float* __restrict__ Wu, const float* __restrict__ Wv,
    const float* __restrict__ Wa, const float* __restrict__ Wb,
    const float* __restrict__ Wc)
{
    int i = blockIdx.x * blockDim.x + threadIdx.x;
    if (i < 16) g_tile_ctr[i] = 0;
    int m = i >> 14;
    int r = i & 16383;
    const float* src = (m == 0) ? Wu : (m == 1) ? Wv : (m == 2) ? Wa : (m == 3) ? Wb : Wc;
    float4 v = __ldg(reinterpret_cast<const float4*>(src) + r);
    reinterpret_cast<float4*>(g_wtf)[i] = tf32_4(v);
}

// ---------------------------------------------------------------------------
// Shared persistent-GEMM pieces
// ---------------------------------------------------------------------------
struct TileAcc { float a[2][8][4]; };

__device__ __forceinline__ void pg_mainloop(
    const float* __restrict__ src, int r0base, int rowClamp,
    const float* sB_sm, float* smem, const uint32_t* sa_base,
    int ar0, int wm, int wn, int g, int t, TileAcc& A)
{
    #pragma unroll
    for (int mt = 0; mt < 2; mt++)
        #pragma unroll
        for (int nt = 0; nt < 8; nt++)
            #pragma unroll
            for (int q = 0; q < 4; q++) A.a[mt][nt][q] = 0.f;

    #pragma unroll
    for (int i = 0; i < 4; i++) {
        int rr = r0base + ar0 + i * 64; if (rr > rowClamp) rr = rowClamp;
        cpa16(sa_base[0] + i * 64 * SA_STRIDE * 4, src + (size_t)rr * H_DIM);
    }
    cpa_commit();

    #pragma unroll
    for (int c = 0; c < 8; c++) {
        if (c < 7) {
            const int nbuf = (c + 1) & 1;
            const int kk = (c + 1) * 32;
            #pragma unroll
            for (int i = 0; i < 4; i++) {
                int rr = r0base + ar0 + i * 64; if (rr > rowClamp) rr = rowClamp;
                cpa16(sa_base[nbuf] + i * 64 * SA_STRIDE * 4, src + (size_t)rr * H_DIM + kk);
            }
            cpa_commit();
            cpa_wait<1>();
        } else {
            cpa_wait<0>();
        }
        __syncthreads();

        const float* sA = smem + PG_A_OFF + (c & 1) * PG_A_BUF;
        const int kg = c * 32;
        #pragma unroll
        for (int ks = 0; ks < 4; ks++) {
            const int kb = ks * 8;
            float bf[8][2];
            #pragma unroll
            for (int nt = 0; nt < 8; nt++) {
                int n = wn * 64 + nt * 8 + g;
                bf[nt][0] = sB_sm[n * EB_STRIDE + kg + kb + t];
                bf[nt][1] = sB_sm[n * EB_STRIDE + kg + kb + t + 4];
            }
            #pragma unroll
            for (int mt = 0; mt < 2; mt++) {
                int m = wm * 32 + mt * 16;
                float a0 = sA[(m + g) * SA_STRIDE + kb + t];
                float a1 = sA[(m + g + 8) * SA_STRIDE + kb + t];
                float a2 = sA[(m + g) * SA_STRIDE + kb + t + 4];
                float a3 = sA[(m + g + 8) * SA_STRIDE + kb + t + 4];
                #pragma unroll
                for (int nt = 0; nt < 8; nt++)
                    mma_tf32(A.a[mt][nt][0], A.a[mt][nt][1], A.a[mt][nt][2], A.a[mt][nt][3],
                             a0, a1, a2, a3, bf[nt][0], bf[nt][1]);
            }
        }
        __syncthreads();
    }
}

__device__ __forceinline__ void pg_load_B(const float* Wrows, uint32_t smem_u32, int tid) {
    #pragma unroll
    for (int i = 0; i < 16; i++) {
        int fi = tid + i * 512;
        int n  = fi >> 6;
        int q  = fi & 63;
        cpa16(smem_u32 + (PG_B_OFF + n * EB_STRIDE + q * 4) * 4,
              Wrows + (size_t)n * H_DIM + q * 4);
    }
    cpa_commit();
}

// ---------------------------------------------------------------------------
// Kernel 1: persistent node GEMM (R14-validated). grid (8, 18).
// ---------------------------------------------------------------------------
__global__ __launch_bounds__(512, 1) void node_gemm_persistent(
    const float* __restrict__ h,
    const float* __restrict__ bu, const float* __restrict__ bv,
    const float* __restrict__ ba, const float* __restrict__ bb,
    int V)
{
    extern __shared__ float smem[];
    const uint32_t smem_u32 = (uint32_t)__cvta_generic_to_shared(smem);
    __shared__ int s_tile;

    const int gidx = blockIdx.x;
    const int m    = gidx >> 1;
    const int ch   = gidx & 1;
    const float* bias = (m == 0) ? bu : (m == 1) ? bv : (m == 2) ? ba : bb;

    const int tid  = threadIdx.x;
    const int w    = tid >> 5;
    const int lane = tid & 31;
    const int g    = lane >> 2;
    const int t    = lane & 3;
    const int wm   = w >> 1;
    const int wn   = w & 1;
    const int ar0  = tid >> 3;
    const int aq   = (tid & 7) * 4;

    const int nTiles = (V + 255) / 256;

    pg_load_B(g_wtf + (size_t)m * 65536 + (size_t)(ch * 128) * H_DIM, smem_u32, tid);

    const uint32_t sa_base[2] = {
        smem_u32 + (PG_A_OFF + 0 * PG_A_BUF + ar0 * SA_STRIDE + aq) * 4,
        smem_u32 + (PG_A_OFF + 1 * PG_A_BUF + ar0 * SA_STRIDE + aq) * 4 };
    const float* sB = smem + PG_B_OFF;
    const float* hsrc = h + aq;

    while (true) {
        if (tid == 0) s_tile = atomicAdd(&g_tile_ctr[2 + gidx], 1);
        __syncthreads();
        const int ti = s_tile;
        if (ti >= nTiles) break;

        const int r0base = ti * 256;
        TileAcc A;
        pg_mainloop(hsrc, r0base, V - 1, sB, smem, sa_base, ar0, wm, wn, g, t, A);

        #pragma unroll
        for (int mt = 0; mt < 2; mt++) {
            #pragma unroll
            for (int nt = 0; nt < 8; nt++) {
                int col = ch * 128 + wn * 64 + nt * 8 + 2 * t;
                int r0 = r0base + wm * 32 + mt * 16 + g;
                float b0v = bias[col], b1v = bias[col + 1];
                if (r0 < V) {
                    float* o = (m == 0) ? (g_agg + (size_t)r0 * H_DIM + col)
                                        : (g_nodebuf + (size_t)r0 * 1024 + m * 256 + col);
                    o[0] = A.a[mt][nt][0] + b0v;
                    o[1] = A.a[mt][nt][1] + b1v;
                }
                if (r0 + 8 < V) {
                    float* o = (m == 0) ? (g_agg + (size_t)(r0 + 8) * H_DIM + col)
                                        : (g_nodebuf + (size_t)(r0 + 8) * 1024 + m * 256 + col);
                    o[0] = A.a[mt][nt][2] + b0v;
                    o[1] = A.a[mt][nt][3] + b1v;
                }
            }
        }
    }
}

// ---------------------------------------------------------------------------
// Kernel 2a: fused edge GEMM. After each tile's mainloop, the block handles
// its own 128 columns end-to-end: e_new = Ce + bc + Ah[dst] + Bh[src],
// gates = sigmoid, red.v2 into agg[src], fp16 e_new store, and per-row LN
// partial sums -> g_lns[half]. Per-column ops only: NO cross-block waits.
// ---------------------------------------------------------------------------
__global__ __launch_bounds__(512, 1) void edge_gemm_fused(
    const float* __restrict__ e,
    const int*   __restrict__ ei,
    const float* __restrict__ bc,
    int E)
{
    extern __shared__ float smem[];
    const uint32_t smem_u32 = (uint32_t)__cvta_generic_to_shared(smem);
    __shared__ int s_tile;
    __shared__ int sSrc[256], sDst[256];
    __shared__ float s_sum[256], s_sq[256];
    __shared__ float sBc[128];

    const int nb = blockIdx.x;
    const int tid  = threadIdx.x;
    const int w    = tid >> 5;
    const int lane = tid & 31;
    const int g    = lane >> 2;
    const int t    = lane & 3;
    const int wm   = w >> 1;
    const int wn   = w & 1;
    const int ar0  = tid >> 3;
    const int aq   = (tid & 7) * 4;

    const int nTiles = E / 256;

    if (tid < 128) sBc[tid] = bc[nb * 128 + tid];

    pg_load_B(g_wtf + 4 * 65536 + (size_t)(nb * 128) * H_DIM, smem_u32, tid);

    const uint32_t sa_base[2] = {
        smem_u32 + (PG_A_OFF + 0 * PG_A_BUF + ar0 * SA_STRIDE + aq) * 4,
        smem_u32 + (PG_A_OFF + 1 * PG_A_BUF + ar0 * SA_STRIDE + aq) * 4 };
    const float* sB = smem + PG_B_OFF;
    const float* esrc = e + aq;

    while (true) {
        if (tid == 0) s_tile = atomicAdd(&g_tile_ctr[nb], 1);
        __syncthreads();
        const int ti = s_tile;
        if (ti >= nTiles) break;

        const int e0 = ti * 256;

        // stage edge indices + zero LN partials (ordered by mainloop's syncs)
        if (tid < 256) {
            sSrc[tid] = __ldg(ei + e0 + tid);
            sDst[tid] = __ldg(ei + E + e0 + tid);
            s_sum[tid] = 0.f;
            s_sq[tid]  = 0.f;
        }

        TileAcc A;
        pg_mainloop(esrc, e0, E - 1, sB, smem, sa_base, ar0, wm, wn, g, t, A);

        // ---- per-column tile epilogue (this block's 128 cols only) ----
        #pragma unroll
        for (int mt = 0; mt < 2; mt++) {
            #pragma unroll
            for (int rh = 0; rh < 2; rh++) {
                const int lr = wm * 32 + mt * 16 + g + rh * 8;   // local row 0..255
                const int er = e0 + lr;
                const int sN = sSrc[lr];
                const int dN = sDst[lr];
                const float* abase = g_nodebuf + (size_t)dN * 1024 + 512;   // Ah[dst]
                const float* bbase = g_nodebuf + (size_t)sN * 1024 + 768;   // Bh[src]
                const float* vbase = g_nodebuf + (size_t)dN * 1024 + 256;   // Vh[dst]
                float* agbase = g_agg + (size_t)sN * H_DIM;
                __half* ebase = g_enew + (size_t)er * H_DIM;

                float lsum = 0.f, lsq = 0.f;
                #pragma unroll
                for (int nt = 0; nt < 8; nt++) {
                    const int lc = wn * 64 + nt * 8 + 2 * t;     // local col 0..127
                    const int gc = nb * 128 + lc;                // global col
                    float2 ah = *reinterpret_cast<const float2*>(abase + gc);
                    float2 bh = *reinterpret_cast<const float2*>(bbase + gc);
                    float2 vh = *reinterpret_cast<const float2*>(vbase + gc);
                    float x0 = A.a[mt][nt][rh * 2]     + sBc[lc]     + ah.x + bh.x;
                    float x1 = A.a[mt][nt][rh * 2 + 1] + sBc[lc + 1] + ah.y + bh.y;
                    lsum += x0 + x1;
                    lsq  += x0 * x0 + x1 * x1;
                    float g0 = 1.f / (1.f + __expf(-x0));
                    float g1 = 1.f / (1.f + __expf(-x1));
                    red_add_v2(agbase + gc, g0 * vh.x, g1 * vh.y);
                    *reinterpret_cast<__half2*>(ebase + gc) =
                        __floats2half2_rn(x0, x1);
                }
                // reduce over the 4 t-lanes (lane bits 0,1)
                lsum += __shfl_xor_sync(0xFFFFFFFFu, lsum, 1);
                lsq  += __shfl_xor_sync(0xFFFFFFFFu, lsq,  1);
                lsum += __shfl_xor_sync(0xFFFFFFFFu, lsum, 2);
                lsq  += __shfl_xor_sync(0xFFFFFFFFu, lsq,  2);
                if (t == 0) {
                    atomicAdd(&s_sum[lr], lsum);
                    atomicAdd(&s_sq[lr],  lsq);
                }
            }
        }
        __syncthreads();
        if (tid < 256)
            g_lns[(size_t)nb * MAXE + e0 + tid] = make_float2(s_sum[tid], s_sq[tid]);
        __syncthreads();
    }
}

// ---------------------------------------------------------------------------
// Kernel 2b: LN-only edge epilogue. Warp per edge: combine the two halves'
// partial sums, normalize fp16 e_new, ReLU, add residual, store e_out.
// ---------------------------------------------------------------------------
__global__ __launch_bounds__(256) void edge_ln_kernel(
    const float* __restrict__ e,
    const float* __restrict__ ge, const float* __restrict__ be,
    float* __restrict__ e_out,
    int E)
{
    __shared__ float sGe[256], sBe[256];
    const int tid = threadIdx.x;
    sGe[tid] = ge[tid]; sBe[tid] = be[tid];
    __syncthreads();

    const int warp = tid >> 5;
    const int lane = tid & 31;
    const int col0 = lane * 8;
    const int er = blockIdx.x * 8 + warp;

    float2 l0 = g_lns[er];
    float2 l1 = g_lns[(size_t)MAXE + er];
    const float sum = l0.x + l1.x;
    const float sq  = l0.y + l1.y;
    const float mu  = sum * (1.f / 256.f);
    const float var = sq * (1.f / 256.f) - mu * mu;
    const float rs  = rsqrtf(var + LN_EPS);

    // fp16 e_new row chunk: 8 halves = 16B = one ldg.128
    const __half2* enp = reinterpret_cast<const __half2*>(g_enew + (size_t)er * H_DIM + col0);
    float4 hraw = __ldcs(reinterpret_cast<const float4*>(enp));
    const __half2* hp = reinterpret_cast<const __half2*>(&hraw);

    const float4* erp = reinterpret_cast<const float4*>(e + (size_t)er * H_DIM + col0);
    float4 r0 = __ldcs(erp), r1 = __ldcs(erp + 1);
    float erv[8];
    erv[0] = r0.x; erv[1] = r0.y; erv[2] = r0.z; erv[3] = r0.w;
    erv[4] = r1.x; erv[5] = r1.y; erv[6] = r1.z; erv[7] = r1.w;

    float x[8];
    #pragma unroll
    for (int q = 0; q < 4; q++) {
        float2 f = __half22float2(hp[q]);
        x[q * 2]     = f.x;
        x[q * 2 + 1] = f.y;
    }

    float4 o0, o1;
    float* ov0 = &o0.x; float* ov1 = &o1.x;
    #pragma unroll
    for (int c = 0; c < 4; c++) {
        float y = (x[c] - mu) * rs * sGe[col0 + c] + sBe[col0 + c];
        y = y > 0.f ? y : 0.f;
        ov0[c] = erv[c] + y;
    }
    #pragma unroll
    for (int c = 0; c < 4; c++) {
        float y = (x[c + 4] - mu) * rs * sGe[col0 + c + 4] + sBe[col0 + c + 4];
        y = y > 0.f ? y : 0.f;
        ov1[c] = erv[c + 4] + y;
    }
    float4* orow = reinterpret_cast<float4*>(e_out + (size_t)er * H_DIM + col0);
    __stcs(orow, o0);
    __stcs(orow + 1, o1);
}

// ---------------------------------------------------------------------------
// Kernel 3: node epilogue — g_agg holds Uh + bias + agg.
// ---------------------------------------------------------------------------
__global__ __launch_bounds__(256) void node_epilogue_kernel(
    const float* __restrict__ h,
    const float* __restrict__ gh, const float* __restrict__ bhv,
    float* __restrict__ h_out, int V)
{
    const int warp = threadIdx.x >> 5;
    const int lane = threadIdx.x & 31;
    const int n = blockIdx.x * 8 + warp;
    if (n >= V) return;
    const int col0 = lane * 8;

    const float4* ag = reinterpret_cast<const float4*>(g_agg + (size_t)n * H_DIM + col0);
    const float4* hr = reinterpret_cast<const float4*>(h     + (size_t)n * H_DIM + col0);

    float4 g0 = __ldcs(ag), g1 = __ldcs(ag + 1);
    float4 h0 = __ldcs(hr), h1 = __ldcs(hr + 1);

    float x[8], hv[8];
    x[0] = g0.x; x[1] = g0.y; x[2] = g0.z; x[3] = g0.w;
    x[4] = g1.x; x[5] = g1.y; x[6] = g1.z; x[7] = g1.w;
    hv[0] = h0.x; hv[1] = h0.y; hv[2] = h0.z; hv[3] = h0.w;
    hv[4] = h1.x; hv[5] = h1.y; hv[6] = h1.z; hv[7] = h1.w;

    float sum = 0.f, sq = 0.f;
    #pragma unroll
    for (int c = 0; c < 8; c++) { sum += x[c]; sq += x[c] * x[c]; }
    #pragma unroll
    for (int off = 16; off > 0; off >>= 1) {
        sum += __shfl_xor_sync(0xFFFFFFFFu, sum, off);
        sq  += __shfl_xor_sync(0xFFFFFFFFu, sq,  off);
    }
    const float mu  = sum * (1.f / 256.f);
    const float var = sq * (1.f / 256.f) - mu * mu;
    const float rs  = rsqrtf(var + LN_EPS);

    float4 o0, o1;
    float* ov0 = &o0.x; float* ov1 = &o1.x;
    #pragma unroll
    for (int c = 0; c < 4; c++) {
        float y = (x[c] - mu) * rs * gh[col0 + c] + bhv[col0 + c];
        y = y > 0.f ? y : 0.f;
        ov0[c] = hv[c] + y;
    }
    #pragma unroll
    for (int c = 0; c < 4; c++) {
        float y = (x[c + 4] - mu) * rs * gh[col0 + c + 4] + bhv[col0 + c + 4];
        y = y > 0.f ? y : 0.f;
        ov1[c] = hv[c + 4] + y;
    }
    float4* o = reinterpret_cast<float4*>(h_out + (size_t)n * H_DIM + col0);
    __stcs(o, o0);
    __stcs(o + 1, o1);
}

// ---------------------------------------------------------------------------
extern "C" void kernel_launch(void* const* d_in, const int* in_sizes, int n_in,
                              void* d_out, int out_size)
{
    const float* h  = (const float*)d_in[0];
    const float* e  = (const float*)d_in[1];
    const int*   ei = (const int*)  d_in[2];
    const float* Wu = (const float*)d_in[3];
    const float* bu = (const float*)d_in[4];
    const float* Wv = (const float*)d_in[5];
    const float* bv = (const float*)d_in[6];
    const float* Wa = (const float*)d_in[7];
    const float* ba = (const float*)d_in[8];
    const float* Wb = (const float*)d_in[9];
    const float* bb = (const float*)d_in[10];
    const float* Wc = (const float*)d_in[11];
    const float* bc = (const float*)d_in[12];
    const float* gh = (const float*)d_in[13];
    const float* bh = (const float*)d_in[14];
    const float* ge = (const float*)d_in[15];
    const float* be = (const float*)d_in[16];

    const int V = in_sizes[0] / H_DIM;
    const int E = in_sizes[1] / H_DIM;

    float* h_out = (float*)d_out;
    float* e_out = (float*)d_out + (size_t)V * H_DIM;

    static int attr_set = 0;
    if (!attr_set) {
        cudaFuncSetAttribute(node_gemm_persistent,
                             cudaFuncAttributeMaxDynamicSharedMemorySize, PG_SMEM_BYTES);
        cudaFuncSetAttribute(edge_gemm_fused,
                             cudaFuncAttributeMaxDynamicSharedMemorySize, PG_SMEM_BYTES);
        attr_set = 1;
    }

    init_kernel<<<320, 256>>>(Wu, Wv, Wa, Wb, Wc);

    dim3 g1(8, 18);
    node_gemm_persistent<<<g1, 512, PG_SMEM_BYTES>>>(h, bu, bv, ba, bb, V);

    dim3 g2(2, 74);
    edge_gemm_fused<<<g2, 512, PG_SMEM_BYTES>>>(e, ei, bc, E);

    edge_ln_kernel<<<E / 8, 256>>>(e, ge, be, e_out, E);

    node_epilogue_kernel<<<(V + 7) / 8, 256>>>(h, gh, bh, h_out, V);
}

// round 16
// speedup vs baseline: 1.4005x; 1.4005x over previous
#include <cuda_runtime.h>
#include <cuda_fp16.h>
#include <cstdint>
#include <cstddef>
#include <math.h>

#define H_DIM 256
#define MAXV 10000
#define MAXE 160000
#define LN_EPS 1e-5f

__device__ float  g_agg[(size_t)MAXV * H_DIM];     // Uh+bias, then += gated agg
__device__ __half g_nbh[(size_t)MAXV * 768];       // fp16 [Vh | Ah | Bh] per node
__device__ __half g_ceh[(size_t)MAXE * H_DIM];     // fp16 Ce
__device__ float  g_wtf[5 * 65536];                // tf32 [Wu|Wv|Wa|Wb|Wc]
__device__ int    g_tile_ctr[16];

__device__ __forceinline__ void red_add_v4(float* addr, float a, float b, float c, float d) {
    asm volatile("red.global.add.v4.f32 [%0], {%1,%2,%3,%4};"
                 :: "l"(addr), "f"(a), "f"(b), "f"(c), "f"(d));
}

__device__ __forceinline__ float to_tf32(float x) {
    float y;
    asm("cvt.rna.tf32.f32 %0, %1;" : "=f"(y) : "f"(x));
    return y;
}

__device__ __forceinline__ float4 tf32_4(float4 v) {
    return make_float4(to_tf32(v.x), to_tf32(v.y), to_tf32(v.z), to_tf32(v.w));
}

__device__ __forceinline__ void mma_tf32(float& d0, float& d1, float& d2, float& d3,
                                         float a0, float a1, float a2, float a3,
                                         float b0, float b1) {
    asm volatile(
        "mma.sync.aligned.m16n8k8.row.col.f32.tf32.tf32.f32 "
        "{%0,%1,%2,%3}, {%4,%5,%6,%7}, {%8,%9}, {%0,%1,%2,%3};\n"
        : "+f"(d0), "+f"(d1), "+f"(d2), "+f"(d3)
        : "r"(__float_as_uint(a0)), "r"(__float_as_uint(a1)),
          "r"(__float_as_uint(a2)), "r"(__float_as_uint(a3)),
          "r"(__float_as_uint(b0)), "r"(__float_as_uint(b1)));
}

__device__ __forceinline__ void cpa16(uint32_t saddr, const void* g) {
    asm volatile("cp.async.cg.shared.global [%0], [%1], 16;" :: "r"(saddr), "l"(g));
}
__device__ __forceinline__ void cpa_commit() {
    asm volatile("cp.async.commit_group;");
}
template <int N>
__device__ __forceinline__ void cpa_wait() {
    asm volatile("cp.async.wait_group %0;" :: "n"(N));
}

#define SA_STRIDE 36
#define EB_STRIDE 260

#define PG_B_OFF 0
#define PG_A_OFF 33280
#define PG_A_BUF 9216
#define PG_SMEM_BYTES 206848

// ---------------------------------------------------------------------------
// Kernel 0: init — tf32 weights + reset counters.
// ---------------------------------------------------------------------------
__global__ void init_kernel(
    const float* __restrict__ Wu, const float* __restrict__ Wv,
    const float* __restrict__ Wa, const float* __restrict__ Wb,
    const float* __restrict__ Wc)
{
    int i = blockIdx.x * blockDim.x + threadIdx.x;
    if (i < 16) g_tile_ctr[i] = 0;
    int m = i >> 14;
    int r = i & 16383;
    const float* src = (m == 0) ? Wu : (m == 1) ? Wv : (m == 2) ? Wa : (m == 3) ? Wb : Wc;
    float4 v = __ldg(reinterpret_cast<const float4*>(src) + r);
    reinterpret_cast<float4*>(g_wtf)[i] = tf32_4(v);
}

// ---------------------------------------------------------------------------
// Shared persistent-GEMM pieces (R14-validated)
// ---------------------------------------------------------------------------
struct TileAcc { float a[2][8][4]; };

__device__ __forceinline__ void pg_mainloop(
    const float* __restrict__ src, int r0base, int rowClamp,
    const float* sB_sm, float* smem, const uint32_t* sa_base,
    int ar0, int wm, int wn, int g, int t, TileAcc& A)
{
    #pragma unroll
    for (int mt = 0; mt < 2; mt++)
        #pragma unroll
        for (int nt = 0; nt < 8; nt++)
            #pragma unroll
            for (int q = 0; q < 4; q++) A.a[mt][nt][q] = 0.f;

    #pragma unroll
    for (int i = 0; i < 4; i++) {
        int rr = r0base + ar0 + i * 64; if (rr > rowClamp) rr = rowClamp;
        cpa16(sa_base[0] + i * 64 * SA_STRIDE * 4, src + (size_t)rr * H_DIM);
    }
    cpa_commit();

    #pragma unroll
    for (int c = 0; c < 8; c++) {
        if (c < 7) {
            const int nbuf = (c + 1) & 1;
            const int kk = (c + 1) * 32;
            #pragma unroll
            for (int i = 0; i < 4; i++) {
                int rr = r0base + ar0 + i * 64; if (rr > rowClamp) rr = rowClamp;
                cpa16(sa_base[nbuf] + i * 64 * SA_STRIDE * 4, src + (size_t)rr * H_DIM + kk);
            }
            cpa_commit();
            cpa_wait<1>();
        } else {
            cpa_wait<0>();
        }
        __syncthreads();

        const float* sA = smem + PG_A_OFF + (c & 1) * PG_A_BUF;
        const int kg = c * 32;
        #pragma unroll
        for (int ks = 0; ks < 4; ks++) {
            const int kb = ks * 8;
            float bf[8][2];
            #pragma unroll
            for (int nt = 0; nt < 8; nt++) {
                int n = wn * 64 + nt * 8 + g;
                bf[nt][0] = sB_sm[n * EB_STRIDE + kg + kb + t];
                bf[nt][1] = sB_sm[n * EB_STRIDE + kg + kb + t + 4];
            }
            #pragma unroll
            for (int mt = 0; mt < 2; mt++) {
                int m = wm * 32 + mt * 16;
                float a0 = sA[(m + g) * SA_STRIDE + kb + t];
                float a1 = sA[(m + g + 8) * SA_STRIDE + kb + t];
                float a2 = sA[(m + g) * SA_STRIDE + kb + t + 4];
                float a3 = sA[(m + g + 8) * SA_STRIDE + kb + t + 4];
                #pragma unroll
                for (int nt = 0; nt < 8; nt++)
                    mma_tf32(A.a[mt][nt][0], A.a[mt][nt][1], A.a[mt][nt][2], A.a[mt][nt][3],
                             a0, a1, a2, a3, bf[nt][0], bf[nt][1]);
            }
        }
        __syncthreads();
    }
}

__device__ __forceinline__ void pg_load_B(const float* Wrows, uint32_t smem_u32, int tid) {
    #pragma unroll
    for (int i = 0; i < 16; i++) {
        int fi = tid + i * 512;
        int n  = fi >> 6;
        int q  = fi & 63;
        cpa16(smem_u32 + (PG_B_OFF + n * EB_STRIDE + q * 4) * 4,
              Wrows + (size_t)n * H_DIM + q * 4);
    }
    cpa_commit();
}

// ---------------------------------------------------------------------------
// Kernel 1: persistent node GEMM. grid (8, 18). m==0 (Uh) -> float g_agg;
// m in {1,2,3} (Vh,Ah,Bh) -> fp16 g_nbh[node][ (m-1)*256 + col ].
// ---------------------------------------------------------------------------
__global__ __launch_bounds__(512, 1) void node_gemm_persistent(
    const float* __restrict__ h,
    const float* __restrict__ bu, const float* __restrict__ bv,
    const float* __restrict__ ba, const float* __restrict__ bb,
    int V)
{
    extern __shared__ float smem[];
    const uint32_t smem_u32 = (uint32_t)__cvta_generic_to_shared(smem);
    __shared__ int s_tile;

    const int gidx = blockIdx.x;
    const int m    = gidx >> 1;
    const int ch   = gidx & 1;
    const float* bias = (m == 0) ? bu : (m == 1) ? bv : (m == 2) ? ba : bb;

    const int tid  = threadIdx.x;
    const int w    = tid >> 5;
    const int lane = tid & 31;
    const int g    = lane >> 2;
    const int t    = lane & 3;
    const int wm   = w >> 1;
    const int wn   = w & 1;
    const int ar0  = tid >> 3;
    const int aq   = (tid & 7) * 4;

    const int nTiles = (V + 255) / 256;

    pg_load_B(g_wtf + (size_t)m * 65536 + (size_t)(ch * 128) * H_DIM, smem_u32, tid);

    const uint32_t sa_base[2] = {
        smem_u32 + (PG_A_OFF + 0 * PG_A_BUF + ar0 * SA_STRIDE + aq) * 4,
        smem_u32 + (PG_A_OFF + 1 * PG_A_BUF + ar0 * SA_STRIDE + aq) * 4 };
    const float* sB = smem + PG_B_OFF;
    const float* hsrc = h + aq;

    while (true) {
        if (tid == 0) s_tile = atomicAdd(&g_tile_ctr[2 + gidx], 1);
        __syncthreads();
        const int ti = s_tile;
        if (ti >= nTiles) break;

        const int r0base = ti * 256;
        TileAcc A;
        pg_mainloop(hsrc, r0base, V - 1, sB, smem, sa_base, ar0, wm, wn, g, t, A);

        #pragma unroll
        for (int mt = 0; mt < 2; mt++) {
            #pragma unroll
            for (int nt = 0; nt < 8; nt++) {
                int col = ch * 128 + wn * 64 + nt * 8 + 2 * t;
                int r0 = r0base + wm * 32 + mt * 16 + g;
                float b0v = bias[col], b1v = bias[col + 1];
                if (r0 < V) {
                    if (m == 0) {
                        float* o = g_agg + (size_t)r0 * H_DIM + col;
                        o[0] = A.a[mt][nt][0] + b0v;
                        o[1] = A.a[mt][nt][1] + b1v;
                    } else {
                        __half2* o = reinterpret_cast<__half2*>(
                            g_nbh + (size_t)r0 * 768 + (m - 1) * 256 + col);
                        *o = __floats2half2_rn(A.a[mt][nt][0] + b0v, A.a[mt][nt][1] + b1v);
                    }
                }
                if (r0 + 8 < V) {
                    if (m == 0) {
                        float* o = g_agg + (size_t)(r0 + 8) * H_DIM + col;
                        o[0] = A.a[mt][nt][2] + b0v;
                        o[1] = A.a[mt][nt][3] + b1v;
                    } else {
                        __half2* o = reinterpret_cast<__half2*>(
                            g_nbh + (size_t)(r0 + 8) * 768 + (m - 1) * 256 + col);
                        *o = __floats2half2_rn(A.a[mt][nt][2] + b0v, A.a[mt][nt][3] + b1v);
                    }
                }
            }
        }
    }
}

// ---------------------------------------------------------------------------
// Kernel 2a: persistent edge GEMM (R14-validated), Ce stored fp16.
// ---------------------------------------------------------------------------
__global__ __launch_bounds__(512, 1) void edge_gemm_kernel(
    const float* __restrict__ e, int E)
{
    extern __shared__ float smem[];
    const uint32_t smem_u32 = (uint32_t)__cvta_generic_to_shared(smem);
    __shared__ int s_tile;

    const int nb = blockIdx.x;
    const int tid  = threadIdx.x;
    const int w    = tid >> 5;
    const int lane = tid & 31;
    const int g    = lane >> 2;
    const int t    = lane & 3;
    const int wm   = w >> 1;
    const int wn   = w & 1;
    const int ar0  = tid >> 3;
    const int aq   = (tid & 7) * 4;

    const int nTiles = E / 256;

    pg_load_B(g_wtf + 4 * 65536 + (size_t)(nb * 128) * H_DIM, smem_u32, tid);

    const uint32_t sa_base[2] = {
        smem_u32 + (PG_A_OFF + 0 * PG_A_BUF + ar0 * SA_STRIDE + aq) * 4,
        smem_u32 + (PG_A_OFF + 1 * PG_A_BUF + ar0 * SA_STRIDE + aq) * 4 };
    const float* sB = smem + PG_B_OFF;
    const float* esrc = e + aq;

    while (true) {
        if (tid == 0) s_tile = atomicAdd(&g_tile_ctr[nb], 1);
        __syncthreads();
        const int ti = s_tile;
        if (ti >= nTiles) break;

        const int e0 = ti * 256;
        TileAcc A;
        pg_mainloop(esrc, e0, E - 1, sB, smem, sa_base, ar0, wm, wn, g, t, A);

        #pragma unroll
        for (int mt = 0; mt < 2; mt++) {
            #pragma unroll
            for (int nt = 0; nt < 8; nt++) {
                int col = nb * 128 + wn * 64 + nt * 8 + 2 * t;
                int r0 = wm * 32 + mt * 16 + g;
                __half2* o0 = reinterpret_cast<__half2*>(g_ceh + (size_t)(e0 + r0) * H_DIM + col);
                __half2* o1 = reinterpret_cast<__half2*>(g_ceh + (size_t)(e0 + r0 + 8) * H_DIM + col);
                *o0 = __floats2half2_rn(A.a[mt][nt][0], A.a[mt][nt][1]);
                *o1 = __floats2half2_rn(A.a[mt][nt][2], A.a[mt][nt][3]);
            }
        }
    }
}

// ---------------------------------------------------------------------------
// Kernel 2b: edge epilogue (warp per edge). fp16 Ce/Ah/Bh/Vh: one ldg.128
// per operand per row chunk instead of two.
// ---------------------------------------------------------------------------
__global__ __launch_bounds__(256) void edge_epilogue_kernel(
    const float* __restrict__ e,
    const int*   __restrict__ ei,
    const float* __restrict__ bc,
    const float* __restrict__ ge, const float* __restrict__ be,
    float* __restrict__ e_out,
    int E)
{
    __shared__ float sBc[256], sGe[256], sBe[256];
    const int tid = threadIdx.x;
    sBc[tid] = bc[tid]; sGe[tid] = ge[tid]; sBe[tid] = be[tid];
    __syncthreads();

    const int warp = tid >> 5;
    const int lane = tid & 31;
    const int col0 = lane * 8;
    const int er = blockIdx.x * 8 + warp;

    const int s = __ldg(ei + er);
    const int d = __ldg(ei + E + er);

    // fp16 operands: 8 halves = 16B = one ldg.128 each
    float4 ceraw = __ldcs(reinterpret_cast<const float4*>(g_ceh + (size_t)er * H_DIM + col0));
    float4 ahraw = __ldg(reinterpret_cast<const float4*>(g_nbh + (size_t)d * 768 + 256 + col0));
    float4 bhraw = __ldg(reinterpret_cast<const float4*>(g_nbh + (size_t)s * 768 + 512 + col0));
    float4 vhraw = __ldg(reinterpret_cast<const float4*>(g_nbh + (size_t)d * 768 + col0));
    const float4* erp = reinterpret_cast<const float4*>(e + (size_t)er * H_DIM + col0);
    float4 r0 = __ldcs(erp), r1 = __ldcs(erp + 1);

    const __half2* cep = reinterpret_cast<const __half2*>(&ceraw);
    const __half2* ahp = reinterpret_cast<const __half2*>(&ahraw);
    const __half2* bhp = reinterpret_cast<const __half2*>(&bhraw);
    const __half2* vhp = reinterpret_cast<const __half2*>(&vhraw);

    float x[8], vhv[8], erv[8];
    #pragma unroll
    for (int q = 0; q < 4; q++) {
        float2 cf = __half22float2(cep[q]);
        float2 af = __half22float2(ahp[q]);
        float2 bf = __half22float2(bhp[q]);
        float2 vf = __half22float2(vhp[q]);
        x[q * 2]     = cf.x + af.x + bf.x;
        x[q * 2 + 1] = cf.y + af.y + bf.y;
        vhv[q * 2]     = vf.x;
        vhv[q * 2 + 1] = vf.y;
    }
    erv[0] = r0.x; erv[1] = r0.y; erv[2] = r0.z; erv[3] = r0.w;
    erv[4] = r1.x; erv[5] = r1.y; erv[6] = r1.z; erv[7] = r1.w;

    float sum = 0.f, sq = 0.f;
    #pragma unroll
    for (int c = 0; c < 8; c++) {
        float xv = x[c] + sBc[col0 + c];
        x[c] = xv;
        sum += xv;
        sq  += xv * xv;
    }

    float gv[8];
    #pragma unroll
    for (int c = 0; c < 8; c++) {
        float gt = 1.f / (1.f + __expf(-x[c]));
        gv[c] = gt * vhv[c];
    }
    float* ag = g_agg + (size_t)s * H_DIM + col0;
    red_add_v4(ag,     gv[0], gv[1], gv[2], gv[3]);
    red_add_v4(ag + 4, gv[4], gv[5], gv[6], gv[7]);

    #pragma unroll
    for (int off = 16; off > 0; off >>= 1) {
        sum += __shfl_xor_sync(0xFFFFFFFFu, sum, off);
        sq  += __shfl_xor_sync(0xFFFFFFFFu, sq,  off);
    }
    const float mu  = sum * (1.f / 256.f);
    const float var = sq * (1.f / 256.f) - mu * mu;
    const float rs  = rsqrtf(var + LN_EPS);

    float4 o0, o1;
    float* ov0 = &o0.x; float* ov1 = &o1.x;
    #pragma unroll
    for (int c = 0; c < 4; c++) {
        float y = (x[c] - mu) * rs * sGe[col0 + c] + sBe[col0 + c];
        y = y > 0.f ? y : 0.f;
        ov0[c] = erv[c] + y;
    }
    #pragma unroll
    for (int c = 0; c < 4; c++) {
        float y = (x[c + 4] - mu) * rs * sGe[col0 + c + 4] + sBe[col0 + c + 4];
        y = y > 0.f ? y : 0.f;
        ov1[c] = erv[c + 4] + y;
    }
    float4* orow = reinterpret_cast<float4*>(e_out + (size_t)er * H_DIM + col0);
    __stcs(orow, o0);
    __stcs(orow + 1, o1);
}

// ---------------------------------------------------------------------------
// Kernel 3: node epilogue — g_agg holds Uh + bias + agg.
// ---------------------------------------------------------------------------
__global__ __launch_bounds__(256) void node_epilogue_kernel(
    const float* __restrict__ h,
    const float* __restrict__ gh, const float* __restrict__ bhv,
    float* __restrict__ h_out, int V)
{
    const int warp = threadIdx.x >> 5;
    const int lane = threadIdx.x & 31;
    const int n = blockIdx.x * 8 + warp;
    if (n >= V) return;
    const int col0 = lane * 8;

    const float4* ag = reinterpret_cast<const float4*>(g_agg + (size_t)n * H_DIM + col0);
    const float4* hr = reinterpret_cast<const float4*>(h     + (size_t)n * H_DIM + col0);

    float4 g0 = __ldcs(ag), g1 = __ldcs(ag + 1);
    float4 h0 = __ldcs(hr), h1 = __ldcs(hr + 1);

    float x[8], hv[8];
    x[0] = g0.x; x[1] = g0.y; x[2] = g0.z; x[3] = g0.w;
    x[4] = g1.x; x[5] = g1.y; x[6] = g1.z; x[7] = g1.w;
    hv[0] = h0.x; hv[1] = h0.y; hv[2] = h0.z; hv[3] = h0.w;
    hv[4] = h1.x; hv[5] = h1.y; hv[6] = h1.z; hv[7] = h1.w;

    float sum = 0.f, sq = 0.f;
    #pragma unroll
    for (int c = 0; c < 8; c++) { sum += x[c]; sq += x[c] * x[c]; }
    #pragma unroll
    for (int off = 16; off > 0; off >>= 1) {
        sum += __shfl_xor_sync(0xFFFFFFFFu, sum, off);
        sq  += __shfl_xor_sync(0xFFFFFFFFu, sq,  off);
    }
    const float mu  = sum * (1.f / 256.f);
    const float var = sq * (1.f / 256.f) - mu * mu;
    const float rs  = rsqrtf(var + LN_EPS);

    float4 o0, o1;
    float* ov0 = &o0.x; float* ov1 = &o1.x;
    #pragma unroll
    for (int c = 0; c < 4; c++) {
        float y = (x[c] - mu) * rs * gh[col0 + c] + bhv[col0 + c];
        y = y > 0.f ? y : 0.f;
        ov0[c] = hv[c] + y;
    }
    #pragma unroll
    for (int c = 0; c < 4; c++) {
        float y = (x[c + 4] - mu) * rs * gh[col0 + c + 4] + bhv[col0 + c + 4];
        y = y > 0.f ? y : 0.f;
        ov1[c] = hv[c + 4] + y;
    }
    float4* o = reinterpret_cast<float4*>(h_out + (size_t)n * H_DIM + col0);
    __stcs(o, o0);
    __stcs(o + 1, o1);
}

// ---------------------------------------------------------------------------
extern "C" void kernel_launch(void* const* d_in, const int* in_sizes, int n_in,
                              void* d_out, int out_size)
{
    const float* h  = (const float*)d_in[0];
    const float* e  = (const float*)d_in[1];
    const int*   ei = (const int*)  d_in[2];
    const float* Wu = (const float*)d_in[3];
    const float* bu = (const float*)d_in[4];
    const float* Wv = (const float*)d_in[5];
    const float* bv = (const float*)d_in[6];
    const float* Wa = (const float*)d_in[7];
    const float* ba = (const float*)d_in[8];
    const float* Wb = (const float*)d_in[9];
    const float* bb = (const float*)d_in[10];
    const float* Wc = (const float*)d_in[11];
    const float* bc = (const float*)d_in[12];
    const float* gh = (const float*)d_in[13];
    const float* bh = (const float*)d_in[14];
    const float* ge = (const float*)d_in[15];
    const float* be = (const float*)d_in[16];

    const int V = in_sizes[0] / H_DIM;
    const int E = in_sizes[1] / H_DIM;

    float* h_out = (float*)d_out;
    float* e_out = (float*)d_out + (size_t)V * H_DIM;

    static int attr_set = 0;
    if (!attr_set) {
        cudaFuncSetAttribute(node_gemm_persistent,
                             cudaFuncAttributeMaxDynamicSharedMemorySize, PG_SMEM_BYTES);
        cudaFuncSetAttribute(edge_gemm_kernel,
                             cudaFuncAttributeMaxDynamicSharedMemorySize, PG_SMEM_BYTES);
        attr_set = 1;
    }

    init_kernel<<<320, 256>>>(Wu, Wv, Wa, Wb, Wc);

    dim3 g1(8, 18);
    node_gemm_persistent<<<g1, 512, PG_SMEM_BYTES>>>(h, bu, bv, ba, bb, V);

    dim3 g2(2, 74);
    edge_gemm_kernel<<<g2, 512, PG_SMEM_BYTES>>>(e, E);

    edge_epilogue_kernel<<<E / 8, 256>>>(e, ei, bc, ge, be, e_out, E);

    node_epilogue_kernel<<<(V + 7) / 8, 256>>>(h, gh, bh, h_out, V);
}

// round 17
// speedup vs baseline: 1.4992x; 1.0705x over previous
#include <cuda_runtime.h>
#include <cuda_fp16.h>
#include <cstdint>
#include <cstddef>
#include <math.h>

#define H_DIM 256
#define MAXV 10000
#define MAXE 160000
#define LN_EPS 1e-5f

__device__ float  g_agg[(size_t)MAXV * H_DIM];     // Uh+bias, then += gated agg
__device__ __half g_nbh[(size_t)MAXV * 768];       // fp16 [Vh | Ah | Bh] per node
__device__ __half g_ceh[(size_t)MAXE * H_DIM];     // fp16 Ce
__device__ __half g_wth[5 * 65536];                // fp16 [Wu|Wv|Wa|Wb|Wc]
__device__ int    g_tile_ctr[16];

__device__ __forceinline__ void red_add_v4(float* addr, float a, float b, float c, float d) {
    asm volatile("red.global.add.v4.f32 [%0], {%1,%2,%3,%4};"
                 :: "l"(addr), "f"(a), "f"(b), "f"(c), "f"(d));
}

__device__ __forceinline__ void mma_f16(float& d0, float& d1, float& d2, float& d3,
                                        uint32_t a0, uint32_t a1, uint32_t a2, uint32_t a3,
                                        uint32_t b0, uint32_t b1) {
    asm volatile(
        "mma.sync.aligned.m16n8k16.row.col.f32.f16.f16.f32 "
        "{%0,%1,%2,%3}, {%4,%5,%6,%7}, {%8,%9}, {%0,%1,%2,%3};\n"
        : "+f"(d0), "+f"(d1), "+f"(d2), "+f"(d3)
        : "r"(a0), "r"(a1), "r"(a2), "r"(a3), "r"(b0), "r"(b1));
}

__device__ __forceinline__ void cpa16(uint32_t saddr, const void* g) {
    asm volatile("cp.async.cg.shared.global [%0], [%1], 16;" :: "r"(saddr), "l"(g));
}
__device__ __forceinline__ void cpa_commit() {
    asm volatile("cp.async.commit_group;");
}
template <int N>
__device__ __forceinline__ void cpa_wait() {
    asm volatile("cp.async.wait_group %0;" :: "n"(N));
}

// B: 128 rows x 264 halves (132 words/row; bank = (4g+t)%32 permutation)
// A: 256 rows x 40 halves per buffer (20 words/row; bank = (20g+t)%32 permutation)
#define SBH_W 132
#define SAH_H 40
#define B_HALVES 33792          // 128*264
#define A_OFF_H  33792
#define A_BUF_H  10240          // 256*40
#define PG16_SMEM_BYTES ((B_HALVES + 2 * A_BUF_H) * 2)   // 108544

// ---------------------------------------------------------------------------
// Kernel 0: init — fp16 weights + reset counters.
// ---------------------------------------------------------------------------
__global__ void init_kernel(
    const float* __restrict__ Wu, const float* __restrict__ Wv,
    const float* __restrict__ Wa, const float* __restrict__ Wb,
    const float* __restrict__ Wc)
{
    int i = blockIdx.x * blockDim.x + threadIdx.x;   // float4 index, 81920 total
    if (i < 16) g_tile_ctr[i] = 0;
    int m = i >> 14;
    int r = i & 16383;
    const float* src = (m == 0) ? Wu : (m == 1) ? Wv : (m == 2) ? Wa : (m == 3) ? Wb : Wc;
    float4 v = __ldg(reinterpret_cast<const float4*>(src) + r);
    union { __half2 q[2]; uint2 u; } cv;
    cv.q[0] = __floats2half2_rn(v.x, v.y);
    cv.q[1] = __floats2half2_rn(v.z, v.w);
    reinterpret_cast<uint2*>(g_wth)[i] = cv.u;
}

// ---------------------------------------------------------------------------
// Shared fp16 persistent-GEMM pieces
// ---------------------------------------------------------------------------
struct TileAcc { float a[2][8][4]; };

__device__ __forceinline__ void pg16_load_B(const __half* Wrows, uint32_t smem_u32, int tid) {
    #pragma unroll
    for (int i = 0; i < 8; i++) {
        int fi = tid + i * 512;          // 8-half chunk id, 4096 total
        int n  = fi >> 5;                // row 0..127
        int q  = fi & 31;                // 8-half group 0..31
        cpa16(smem_u32 + (n * 264 + q * 8) * 2,
              Wrows + (size_t)n * H_DIM + q * 8);
    }
    cpa_commit();
}

// Full 256x128 tile: A from fp32 src (rows r0base.., clamped), B resident fp16.
__device__ __forceinline__ void pg16_mainloop(
    const float* __restrict__ src, int r0base, int rowClamp,
    __half* smemh, int tid, int wm, int wn, int g, int t, TileAcc& A)
{
    #pragma unroll
    for (int mt = 0; mt < 2; mt++)
        #pragma unroll
        for (int nt = 0; nt < 8; nt++)
            #pragma unroll
            for (int q = 0; q < 4; q++) A.a[mt][nt][q] = 0.f;

    const int ar0 = tid >> 1;            // staged row 0..255
    const int acb = (tid & 1) * 16;      // col sub-base within 32-chunk
    int rr = r0base + ar0; if (rr > rowClamp) rr = rowClamp;
    const float* arow = src + (size_t)rr * H_DIM + acb;

    const uint32_t* sBw = reinterpret_cast<const uint32_t*>(smemh);

    float4 v0, v1, v2, v3;
    #define LDGC(c) do { \
        const float4* p = reinterpret_cast<const float4*>(arow + (c) * 32); \
        v0 = __ldg(p); v1 = __ldg(p + 1); v2 = __ldg(p + 2); v3 = __ldg(p + 3); } while (0)
    #define STSC(buf) do { \
        union { __half2 q[8]; uint4 u[2]; } cv; \
        cv.q[0] = __floats2half2_rn(v0.x, v0.y); cv.q[1] = __floats2half2_rn(v0.z, v0.w); \
        cv.q[2] = __floats2half2_rn(v1.x, v1.y); cv.q[3] = __floats2half2_rn(v1.z, v1.w); \
        cv.q[4] = __floats2half2_rn(v2.x, v2.y); cv.q[5] = __floats2half2_rn(v2.z, v2.w); \
        cv.q[6] = __floats2half2_rn(v3.x, v3.y); cv.q[7] = __floats2half2_rn(v3.z, v3.w); \
        uint4* dst = reinterpret_cast<uint4*>(smemh + A_OFF_H + (buf) * A_BUF_H + ar0 * SAH_H + acb); \
        dst[0] = cv.u[0]; dst[1] = cv.u[1]; } while (0)

    LDGC(0);
    STSC(0);

    #pragma unroll
    for (int c = 0; c < 8; c++) {
        if (c < 7) LDGC(c + 1);
        __syncthreads();

        const uint32_t* sAw = reinterpret_cast<const uint32_t*>(
            smemh + A_OFF_H + (c & 1) * A_BUF_H);
        #pragma unroll
        for (int ks = 0; ks < 2; ks++) {
            const int kwA = ks * 8 + t;            // A word within this chunk's row
            const int kwB = c * 16 + ks * 8 + t;   // B word within full-K row
            uint32_t bf[8][2];
            #pragma unroll
            for (int nt = 0; nt < 8; nt++) {
                int n = wn * 64 + nt * 8 + g;
                bf[nt][0] = sBw[n * SBH_W + kwB];
                bf[nt][1] = sBw[n * SBH_W + kwB + 4];
            }
            #pragma unroll
            for (int mt = 0; mt < 2; mt++) {
                int m = wm * 32 + mt * 16 + g;
                uint32_t a0 = sAw[m * 20 + kwA];
                uint32_t a1 = sAw[(m + 8) * 20 + kwA];
                uint32_t a2 = sAw[m * 20 + kwA + 4];
                uint32_t a3 = sAw[(m + 8) * 20 + kwA + 4];
                #pragma unroll
                for (int nt = 0; nt < 8; nt++)
                    mma_f16(A.a[mt][nt][0], A.a[mt][nt][1], A.a[mt][nt][2], A.a[mt][nt][3],
                            a0, a1, a2, a3, bf[nt][0], bf[nt][1]);
            }
        }
        if (c < 7) STSC((c + 1) & 1);
    }
    #undef LDGC
    #undef STSC
}

// ---------------------------------------------------------------------------
// Kernel 1: persistent node GEMM (fp16). grid (8, 18).
// m==0 (Uh) -> float g_agg; m in {1,2,3} -> fp16 g_nbh.
// ---------------------------------------------------------------------------
__global__ __launch_bounds__(512, 1) void node_gemm_persistent(
    const float* __restrict__ h,
    const float* __restrict__ bu, const float* __restrict__ bv,
    const float* __restrict__ ba, const float* __restrict__ bb,
    int V)
{
    extern __shared__ __half smemh[];
    const uint32_t smem_u32 = (uint32_t)__cvta_generic_to_shared(smemh);
    __shared__ int s_tile;

    const int gidx = blockIdx.x;
    const int m    = gidx >> 1;
    const int ch   = gidx & 1;
    const float* bias = (m == 0) ? bu : (m == 1) ? bv : (m == 2) ? ba : bb;

    const int tid  = threadIdx.x;
    const int w    = tid >> 5;
    const int lane = tid & 31;
    const int g    = lane >> 2;
    const int t    = lane & 3;
    const int wm   = w >> 1;
    const int wn   = w & 1;

    const int nTiles = (V + 255) / 256;

    pg16_load_B(g_wth + (size_t)m * 65536 + (size_t)(ch * 128) * H_DIM, smem_u32, tid);
    cpa_wait<0>();

    while (true) {
        if (tid == 0) s_tile = atomicAdd(&g_tile_ctr[2 + gidx], 1);
        __syncthreads();
        const int ti = s_tile;
        if (ti >= nTiles) break;

        const int r0base = ti * 256;
        TileAcc A;
        pg16_mainloop(h, r0base, V - 1, smemh, tid, wm, wn, g, t, A);

        #pragma unroll
        for (int mt = 0; mt < 2; mt++) {
            #pragma unroll
            for (int nt = 0; nt < 8; nt++) {
                int col = ch * 128 + wn * 64 + nt * 8 + 2 * t;
                int r0 = r0base + wm * 32 + mt * 16 + g;
                float b0v = bias[col], b1v = bias[col + 1];
                if (r0 < V) {
                    if (m == 0) {
                        float* o = g_agg + (size_t)r0 * H_DIM + col;
                        o[0] = A.a[mt][nt][0] + b0v;
                        o[1] = A.a[mt][nt][1] + b1v;
                    } else {
                        __half2* o = reinterpret_cast<__half2*>(
                            g_nbh + (size_t)r0 * 768 + (m - 1) * 256 + col);
                        *o = __floats2half2_rn(A.a[mt][nt][0] + b0v, A.a[mt][nt][1] + b1v);
                    }
                }
                if (r0 + 8 < V) {
                    if (m == 0) {
                        float* o = g_agg + (size_t)(r0 + 8) * H_DIM + col;
                        o[0] = A.a[mt][nt][2] + b0v;
                        o[1] = A.a[mt][nt][3] + b1v;
                    } else {
                        __half2* o = reinterpret_cast<__half2*>(
                            g_nbh + (size_t)(r0 + 8) * 768 + (m - 1) * 256 + col);
                        *o = __floats2half2_rn(A.a[mt][nt][2] + b0v, A.a[mt][nt][3] + b1v);
                    }
                }
            }
        }
    }
}

// ---------------------------------------------------------------------------
// Kernel 2a: persistent edge GEMM (fp16), Ce stored fp16. grid (2, 74).
// ---------------------------------------------------------------------------
__global__ __launch_bounds__(512, 1) void edge_gemm_kernel(
    const float* __restrict__ e, int E)
{
    extern __shared__ __half smemh[];
    const uint32_t smem_u32 = (uint32_t)__cvta_generic_to_shared(smemh);
    __shared__ int s_tile;

    const int nb = blockIdx.x;
    const int tid  = threadIdx.x;
    const int w    = tid >> 5;
    const int lane = tid & 31;
    const int g    = lane >> 2;
    const int t    = lane & 3;
    const int wm   = w >> 1;
    const int wn   = w & 1;

    const int nTiles = E / 256;

    pg16_load_B(g_wth + 4 * 65536 + (size_t)(nb * 128) * H_DIM, smem_u32, tid);
    cpa_wait<0>();

    while (true) {
        if (tid == 0) s_tile = atomicAdd(&g_tile_ctr[nb], 1);
        __syncthreads();
        const int ti = s_tile;
        if (ti >= nTiles) break;

        const int e0 = ti * 256;
        TileAcc A;
        pg16_mainloop(e, e0, E - 1, smemh, tid, wm, wn, g, t, A);

        #pragma unroll
        for (int mt = 0; mt < 2; mt++) {
            #pragma unroll
            for (int nt = 0; nt < 8; nt++) {
                int col = nb * 128 + wn * 64 + nt * 8 + 2 * t;
                int r0 = wm * 32 + mt * 16 + g;
                __half2* o0 = reinterpret_cast<__half2*>(g_ceh + (size_t)(e0 + r0) * H_DIM + col);
                __half2* o1 = reinterpret_cast<__half2*>(g_ceh + (size_t)(e0 + r0 + 8) * H_DIM + col);
                *o0 = __floats2half2_rn(A.a[mt][nt][0], A.a[mt][nt][1]);
                *o1 = __floats2half2_rn(A.a[mt][nt][2], A.a[mt][nt][3]);
            }
        }
    }
}

// ---------------------------------------------------------------------------
// Kernel 2b: edge epilogue (R16-validated; fp16 operands)
// ---------------------------------------------------------------------------
__global__ __launch_bounds__(256) void edge_epilogue_kernel(
    const float* __restrict__ e,
    const int*   __restrict__ ei,
    const float* __restrict__ bc,
    const float* __restrict__ ge, const float* __restrict__ be,
    float* __restrict__ e_out,
    int E)
{
    __shared__ float sBc[256], sGe[256], sBe[256];
    const int tid = threadIdx.x;
    sBc[tid] = bc[tid]; sGe[tid] = ge[tid]; sBe[tid] = be[tid];
    __syncthreads();

    const int warp = tid >> 5;
    const int lane = tid & 31;
    const int col0 = lane * 8;
    const int er = blockIdx.x * 8 + warp;

    const int s = __ldg(ei + er);
    const int d = __ldg(ei + E + er);

    float4 ceraw = __ldcs(reinterpret_cast<const float4*>(g_ceh + (size_t)er * H_DIM + col0));
    float4 ahraw = __ldg(reinterpret_cast<const float4*>(g_nbh + (size_t)d * 768 + 256 + col0));
    float4 bhraw = __ldg(reinterpret_cast<const float4*>(g_nbh + (size_t)s * 768 + 512 + col0));
    float4 vhraw = __ldg(reinterpret_cast<const float4*>(g_nbh + (size_t)d * 768 + col0));
    const float4* erp = reinterpret_cast<const float4*>(e + (size_t)er * H_DIM + col0);
    float4 r0 = __ldcs(erp), r1 = __ldcs(erp + 1);

    const __half2* cep = reinterpret_cast<const __half2*>(&ceraw);
    const __half2* ahp = reinterpret_cast<const __half2*>(&ahraw);
    const __half2* bhp = reinterpret_cast<const __half2*>(&bhraw);
    const __half2* vhp = reinterpret_cast<const __half2*>(&vhraw);

    float x[8], vhv[8], erv[8];
    #pragma unroll
    for (int q = 0; q < 4; q++) {
        float2 cf = __half22float2(cep[q]);
        float2 af = __half22float2(ahp[q]);
        float2 bf = __half22float2(bhp[q]);
        float2 vf = __half22float2(vhp[q]);
        x[q * 2]     = cf.x + af.x + bf.x;
        x[q * 2 + 1] = cf.y + af.y + bf.y;
        vhv[q * 2]     = vf.x;
        vhv[q * 2 + 1] = vf.y;
    }
    erv[0] = r0.x; erv[1] = r0.y; erv[2] = r0.z; erv[3] = r0.w;
    erv[4] = r1.x; erv[5] = r1.y; erv[6] = r1.z; erv[7] = r1.w;

    float sum = 0.f, sq = 0.f;
    #pragma unroll
    for (int c = 0; c < 8; c++) {
        float xv = x[c] + sBc[col0 + c];
        x[c] = xv;
        sum += xv;
        sq  += xv * xv;
    }

    float gv[8];
    #pragma unroll
    for (int c = 0; c < 8; c++) {
        float gt = 1.f / (1.f + __expf(-x[c]));
        gv[c] = gt * vhv[c];
    }
    float* ag = g_agg + (size_t)s * H_DIM + col0;
    red_add_v4(ag,     gv[0], gv[1], gv[2], gv[3]);
    red_add_v4(ag + 4, gv[4], gv[5], gv[6], gv[7]);

    #pragma unroll
    for (int off = 16; off > 0; off >>= 1) {
        sum += __shfl_xor_sync(0xFFFFFFFFu, sum, off);
        sq  += __shfl_xor_sync(0xFFFFFFFFu, sq,  off);
    }
    const float mu  = sum * (1.f / 256.f);
    const float var = sq * (1.f / 256.f) - mu * mu;
    const float rs  = rsqrtf(var + LN_EPS);

    float4 o0, o1;
    float* ov0 = &o0.x; float* ov1 = &o1.x;
    #pragma unroll
    for (int c = 0; c < 4; c++) {
        float y = (x[c] - mu) * rs * sGe[col0 + c] + sBe[col0 + c];
        y = y > 0.f ? y : 0.f;
        ov0[c] = erv[c] + y;
    }
    #pragma unroll
    for (int c = 0; c < 4; c++) {
        float y = (x[c + 4] - mu) * rs * sGe[col0 + c + 4] + sBe[col0 + c + 4];
        y = y > 0.f ? y : 0.f;
        ov1[c] = erv[c + 4] + y;
    }
    float4* orow = reinterpret_cast<float4*>(e_out + (size_t)er * H_DIM + col0);
    __stcs(orow, o0);
    __stcs(orow + 1, o1);
}

// ---------------------------------------------------------------------------
// Kernel 3: node epilogue — g_agg holds Uh + bias + agg.
// ---------------------------------------------------------------------------
__global__ __launch_bounds__(256) void node_epilogue_kernel(
    const float* __restrict__ h,
    const float* __restrict__ gh, const float* __restrict__ bhv,
    float* __restrict__ h_out, int V)
{
    const int warp = threadIdx.x >> 5;
    const int lane = threadIdx.x & 31;
    const int n = blockIdx.x * 8 + warp;
    if (n >= V) return;
    const int col0 = lane * 8;

    const float4* ag = reinterpret_cast<const float4*>(g_agg + (size_t)n * H_DIM + col0);
    const float4* hr = reinterpret_cast<const float4*>(h     + (size_t)n * H_DIM + col0);

    float4 g0 = __ldcs(ag), g1 = __ldcs(ag + 1);
    float4 h0 = __ldcs(hr), h1 = __ldcs(hr + 1);

    float x[8], hv[8];
    x[0] = g0.x; x[1] = g0.y; x[2] = g0.z; x[3] = g0.w;
    x[4] = g1.x; x[5] = g1.y; x[6] = g1.z; x[7] = g1.w;
    hv[0] = h0.x; hv[1] = h0.y; hv[2] = h0.z; hv[3] = h0.w;
    hv[4] = h1.x; hv[5] = h1.y; hv[6] = h1.z; hv[7] = h1.w;

    float sum = 0.f, sq = 0.f;
    #pragma unroll
    for (int c = 0; c < 8; c++) { sum += x[c]; sq += x[c] * x[c]; }
    #pragma unroll
    for (int off = 16; off > 0; off >>= 1) {
        sum += __shfl_xor_sync(0xFFFFFFFFu, sum, off);
        sq  += __shfl_xor_sync(0xFFFFFFFFu, sq,  off);
    }
    const float mu  = sum * (1.f / 256.f);
    const float var = sq * (1.f / 256.f) - mu * mu;
    const float rs  = rsqrtf(var + LN_EPS);

    float4 o0, o1;
    float* ov0 = &o0.x; float* ov1 = &o1.x;
    #pragma unroll
    for (int c = 0; c < 4; c++) {
        float y = (x[c] - mu) * rs * gh[col0 + c] + bhv[col0 + c];
        y = y > 0.f ? y : 0.f;
        ov0[c] = hv[c] + y;
    }
    #pragma unroll
    for (int c = 0; c < 4; c++) {
        float y = (x[c + 4] - mu) * rs * gh[col0 + c + 4] + bhv[col0 + c + 4];
        y = y > 0.f ? y : 0.f;
        ov1[c] = hv[c + 4] + y;
    }
    float4* o = reinterpret_cast<float4*>(h_out + (size_t)n * H_DIM + col0);
    __stcs(o, o0);
    __stcs(o + 1, o1);
}

// ---------------------------------------------------------------------------
extern "C" void kernel_launch(void* const* d_in, const int* in_sizes, int n_in,
                              void* d_out, int out_size)
{
    const float* h  = (const float*)d_in[0];
    const float* e  = (const float*)d_in[1];
    const int*   ei = (const int*)  d_in[2];
    const float* Wu = (const float*)d_in[3];
    const float* bu = (const float*)d_in[4];
    const float* Wv = (const float*)d_in[5];
    const float* bv = (const float*)d_in[6];
    const float* Wa = (const float*)d_in[7];
    const float* ba = (const float*)d_in[8];
    const float* Wb = (const float*)d_in[9];
    const float* bb = (const float*)d_in[10];
    const float* Wc = (const float*)d_in[11];
    const float* bc = (const float*)d_in[12];
    const float* gh = (const float*)d_in[13];
    const float* bh = (const float*)d_in[14];
    const float* ge = (const float*)d_in[15];
    const float* be = (const float*)d_in[16];

    const int V = in_sizes[0] / H_DIM;
    const int E = in_sizes[1] / H_DIM;

    float* h_out = (float*)d_out;
    float* e_out = (float*)d_out + (size_t)V * H_DIM;

    static int attr_set = 0;
    if (!attr_set) {
        cudaFuncSetAttribute(node_gemm_persistent,
                             cudaFuncAttributeMaxDynamicSharedMemorySize, PG16_SMEM_BYTES);
        cudaFuncSetAttribute(edge_gemm_kernel,
                             cudaFuncAttributeMaxDynamicSharedMemorySize, PG16_SMEM_BYTES);
        attr_set = 1;
    }

    init_kernel<<<320, 256>>>(Wu, Wv, Wa, Wb, Wc);

    dim3 g1(8, 18);
    node_gemm_persistent<<<g1, 512, PG16_SMEM_BYTES>>>(h, bu, bv, ba, bb, V);

    dim3 g2(2, 74);
    edge_gemm_kernel<<<g2, 512, PG16_SMEM_BYTES>>>(e, E);

    edge_epilogue_kernel<<<E / 8, 256>>>(e, ei, bc, ge, be, e_out, E);

    node_epilogue_kernel<<<(V + 7) / 8, 256>>>(h, gh, bh, h_out, V);
}